// round 5
// baseline (speedup 1.0000x reference)
#include <cuda_runtime.h>
#include <math.h>

// Problem constants
#define BDIM   8
#define LLEAF  16384
#define NNODE  32767      // 2*L - 1
#define NINT   16383      // internal nodes = L - 1
#define DH     256
#define MAXN   16384

// Static device scratch (heap allocation is forbidden by the harness rules).
// pre_iou : 8 * 32767 * 768 = 201,320,448 floats (~805 MB)
// pre_f   : 8 * 16383 * 256 =  33,552,384 floats (~134 MB)
// h/c ping-pong: 2 * (8 * 16384 * 256) floats each (~268 MB each pair-set)
// giou    : 8 * 8192 * 768  =  50,331,648 floats (~201 MB)
// gf      : 8 * 16384 * 256 =  33,554,432 floats (~134 MB)
__device__ float g_pre_iou[201320448];
__device__ float g_pre_f[33552384];
__device__ float g_h[2][33554432];
__device__ float g_c[2][33554432];
__device__ float g_giou[50331648];
__device__ float g_gf[33554432];

__device__ __forceinline__ float sigm(float v) { return 1.0f / (1.0f + expf(-v)); }

// ---------------------------------------------------------------------------
// Tiled fp32 GEMM: C[M,Ncols] = A' @ Bm (+ bias). K fixed at 256.
// BM=BN=128, BK=8, 256 threads, 8x8 per-thread micro-tile.
//
// Logical A row m decomposes as m = b*nlev + k (b = batch, k = row-in-level).
//   pairsum == 0 : A' row = A[(b*astride + k) * 256]
//   pairsum == 1 : A' row = A[(b*astride + 2k)*256] + A[(b*astride + 2k+1)*256]
// ---------------------------------------------------------------------------
__global__ __launch_bounds__(256, 2)
void gemm_kernel(const float* __restrict__ A, const float* __restrict__ Bm,
                 const float* __restrict__ bias, float* __restrict__ C,
                 int M, int Ncols, int nlev, int astride, int pairsum) {
    __shared__ float As[8][132];   // [BK][BM+4] : pad kills store conflicts
    __shared__ float Bs[8][128];   // [BK][BN]

    const int m0 = blockIdx.y * 128;
    const int n0 = blockIdx.x * 128;
    const int tid = threadIdx.x;
    const int ty = tid >> 4;       // 0..15
    const int tx = tid & 15;       // 0..15

    float acc[8][8];
#pragma unroll
    for (int i = 0; i < 8; i++)
#pragma unroll
        for (int j = 0; j < 8; j++) acc[i][j] = 0.0f;

    // A tile loader: 2 threads per row, one float4 each (8 k's per row)
    const int ar = tid >> 1;          // 0..127
    const int ak = (tid & 1) * 4;     // 0 or 4
    // B tile loader: 32 threads per k-row, one float4 each
    const int br = tid >> 5;          // 0..7
    const int bc = (tid & 31) * 4;    // 0..124

    const int gm_a = m0 + ar;
    const bool avalid = (gm_a < M);
    size_t abase = 0, abase2 = 0;
    if (avalid) {
        int b = gm_a / nlev;
        int k = gm_a - b * nlev;
        size_t row = (size_t)b * astride + (pairsum ? 2 * k : k);
        abase = row * 256;
        abase2 = abase + 256;          // sibling row (pairsum only)
    }

    for (int kt = 0; kt < 256; kt += 8) {
        float4 av = make_float4(0.f, 0.f, 0.f, 0.f);
        if (avalid) {
            av = *(const float4*)(A + abase + kt + ak);
            if (pairsum) {
                float4 a1 = *(const float4*)(A + abase2 + kt + ak);
                av.x += a1.x; av.y += a1.y; av.z += a1.z; av.w += a1.w;
            }
        }
        As[ak + 0][ar] = av.x;
        As[ak + 1][ar] = av.y;
        As[ak + 2][ar] = av.z;
        As[ak + 3][ar] = av.w;

        *(float4*)&Bs[br][bc] =
            *(const float4*)(Bm + (size_t)(kt + br) * Ncols + n0 + bc);

        __syncthreads();

#pragma unroll
        for (int kk = 0; kk < 8; kk++) {
            float a[8], b[8];
            *(float4*)&a[0] = *(const float4*)&As[kk][ty * 8];
            *(float4*)&a[4] = *(const float4*)&As[kk][ty * 8 + 4];
            *(float4*)&b[0] = *(const float4*)&Bs[kk][tx * 8];
            *(float4*)&b[4] = *(const float4*)&Bs[kk][tx * 8 + 4];
#pragma unroll
            for (int i = 0; i < 8; i++)
#pragma unroll
                for (int j = 0; j < 8; j++)
                    acc[i][j] = fmaf(a[i], b[j], acc[i][j]);
        }
        __syncthreads();
    }

#pragma unroll
    for (int i = 0; i < 8; i++) {
        int gm = m0 + ty * 8 + i;
        if (gm >= M) continue;
        size_t crow = (size_t)gm * Ncols + n0 + tx * 8;
        if (bias) {
            const float* bp = bias + n0 + tx * 8;
#pragma unroll
            for (int j = 0; j < 8; j++) acc[i][j] += bp[j];
        }
        *(float4*)(C + crow)     = *(float4*)&acc[i][0];
        *(float4*)(C + crow + 4) = *(float4*)&acc[i][4];
    }
}

// ---------------------------------------------------------------------------
// Leaf activation: c = sig(i)*tanh(u); h = sig(o)*tanh(c)  -> ping buffer 0
// ---------------------------------------------------------------------------
__global__ void leaf_kernel() {
    size_t gid = (size_t)blockIdx.x * blockDim.x + threadIdx.x;  // B*L*H threads
    int j = (int)(gid & 255);
    size_t m = gid >> 8;            // b*L + k
    int b = (int)(m >> 14);         // /16384
    int k = (int)(m & 16383);
    size_t prerow = ((size_t)b * NNODE + (LLEAF - 1) + k) * 768;
    float iv = g_pre_iou[prerow + j];
    float ov = g_pre_iou[prerow + 256 + j];
    float uv = g_pre_iou[prerow + 512 + j];
    float c = sigm(iv) * tanhf(uv);
    float h = sigm(ov) * tanhf(c);
    size_t idx = ((size_t)b * MAXN + k) * DH + j;
    g_h[0][idx] = h;
    g_c[0][idx] = c;
}

// ---------------------------------------------------------------------------
// Per-level combine: gates + forget-weighted child cells.
// ---------------------------------------------------------------------------
__global__ void combine_kernel(int n, int pin, int pout) {
    size_t gid = (size_t)blockIdx.x * blockDim.x + threadIdx.x;
    size_t total = (size_t)BDIM * n * DH;
    if (gid >= total) return;
    int j = (int)(gid & 255);
    size_t m = gid >> 8;            // b*n + k
    int b = (int)(m / (unsigned)n);
    int k = (int)(m - (size_t)b * n);
    int node = (n - 1) + k;         // node index within batch (internal: 0..NINT-1)

    size_t prow = ((size_t)b * NNODE + node) * 768;
    size_t grow = m * 768;
    float iv = g_pre_iou[prow + j]       + g_giou[grow + j];
    float ov = g_pre_iou[prow + 256 + j] + g_giou[grow + 256 + j];
    float uv = g_pre_iou[prow + 512 + j] + g_giou[grow + 512 + j];
    float fb = g_pre_f[((size_t)b * NINT + node) * 256 + j];

    size_t gf0 = ((size_t)b * (2 * n) + 2 * k) * 256 + j;
    float f0 = sigm(fb + g_gf[gf0]);
    float f1 = sigm(fb + g_gf[gf0 + 256]);

    size_t cbase = ((size_t)b * MAXN + 2 * k) * 256 + j;
    float c0 = g_c[pin][cbase];
    float c1 = g_c[pin][cbase + 256];

    float cn = sigm(iv) * tanhf(uv) + f0 * c0 + f1 * c1;
    float hn = sigm(ov) * tanhf(cn);

    size_t outi = ((size_t)b * MAXN + k) * 256 + j;
    g_h[pout][outi] = hn;
    g_c[pout][outi] = cn;
}

// ---------------------------------------------------------------------------
// Output: out[b, 0:256] = h_root, out[b, 256:512] = c_root
// ---------------------------------------------------------------------------
__global__ void final_kernel(int p, float* __restrict__ out) {
    int gid = blockIdx.x * blockDim.x + threadIdx.x;
    if (gid >= BDIM * 512) return;
    int b = gid >> 9;
    int j = gid & 511;
    size_t base = ((size_t)b * MAXN) * 256;
    out[gid] = (j < 256) ? g_h[p][base + j] : g_c[p][base + j - 256];
}

// ---------------------------------------------------------------------------
extern "C" void kernel_launch(void* const* d_in, const int* in_sizes, int n_in,
                              void* d_out, int out_size) {
    const float* x     = (const float*)d_in[0];
    const float* W_iou = (const float*)d_in[1];
    const float* b_iou = (const float*)d_in[2];
    const float* U_iou = (const float*)d_in[3];
    const float* W_f   = (const float*)d_in[4];
    const float* b_f   = (const float*)d_in[5];
    const float* U_f   = (const float*)d_in[6];
    float* out = (float*)d_out;

    float *pPreIou, *pPreF, *pH, *pGiou, *pGf;
    cudaGetSymbolAddress((void**)&pPreIou, g_pre_iou);
    cudaGetSymbolAddress((void**)&pPreF, g_pre_f);
    cudaGetSymbolAddress((void**)&pH, g_h);
    cudaGetSymbolAddress((void**)&pGiou, g_giou);
    cudaGetSymbolAddress((void**)&pGf, g_gf);

    // 1) Input projections:
    //    pre_iou = x(all N nodes) @ W_iou + b_iou   [B*NNODE, 768]
    //    pre_f   = x(internal nodes) @ W_f + b_f    [B*NINT, 256]
    {
        int M = BDIM * NNODE;  // 262136
        dim3 grid(768 / 128, (M + 127) / 128);
        gemm_kernel<<<grid, 256>>>(x, W_iou, b_iou, pPreIou, M, 768,
                                   NNODE, NNODE, 0);
    }
    {
        int M = BDIM * NINT;   // 131064  (internal nodes = x rows 0..L-2)
        dim3 grid(256 / 128, (M + 127) / 128);
        gemm_kernel<<<grid, 256>>>(x, W_f, b_f, pPreF, M, 256,
                                   NINT, NNODE, 0);
    }

    // 2) Leaf activations -> ping buffer 0
    leaf_kernel<<<(BDIM * LLEAF * DH) / 256, 256>>>();

    // 3) 14 levels, halving each time
    int p = 0;
    for (int n = LLEAF / 2; n >= 1; n >>= 1) {
        int pin = p, pout = 1 - p;
        const float* hin = pH + (size_t)pin * 33554432;

        // giou = (h_left + h_right) @ U_iou   [B*n, 768]
        int M1 = BDIM * n;
        dim3 g1(768 / 128, (M1 + 127) / 128);
        gemm_kernel<<<g1, 256>>>(hin, U_iou, nullptr, pGiou, M1, 768,
                                 n, MAXN, 1);

        // gf = h_children @ U_f               [B*2n, 256]
        int M2 = BDIM * 2 * n;
        dim3 g2(256 / 128, (M2 + 127) / 128);
        gemm_kernel<<<g2, 256>>>(hin, U_f, nullptr, pGf, M2, 256,
                                 2 * n, MAXN, 0);

        size_t tot = (size_t)BDIM * n * DH;
        combine_kernel<<<(unsigned)((tot + 255) / 256), 256>>>(n, pin, pout);
        p = pout;
    }

    // 4) Emit root h,c
    final_kernel<<<16, 256>>>(p, out);
}

// round 8
// speedup vs baseline: 1.7991x; 1.7991x over previous
#include <cuda_runtime.h>
#include <cuda_bf16.h>
#include <math.h>
#include <stdint.h>

// Problem constants
#define BDIM   8
#define LLEAF  16384
#define NNODE  32767      // 2*L - 1
#define NINT   16383      // internal nodes = L - 1
#define DH     256
#define MAXN   16384

// ---------------------------------------------------------------------------
// Static device scratch
// ---------------------------------------------------------------------------
__device__ float g_pre_iou[201320448];   // 8*32767*768
__device__ float g_pre_f[33552384];      // 8*16383*256
__device__ float g_h[2][33554432];       // ping-pong h
__device__ float g_c[2][33554432];       // ping-pong c
__device__ float g_giou[50331648];       // 8*8192*768
__device__ float g_gf[33554432];         // 8*16384*256

// Pre-split, transposed weights: Wt[n][k] = W[k][n], hi/lo bf16
__device__ __nv_bfloat16 g_wiou_hi[196608], g_wiou_lo[196608];   // 768x256
__device__ __nv_bfloat16 g_uiou_hi[196608], g_uiou_lo[196608];   // 768x256
__device__ __nv_bfloat16 g_wf_hi[65536],   g_wf_lo[65536];       // 256x256
__device__ __nv_bfloat16 g_uf_hi[65536],   g_uf_lo[65536];       // 256x256

__device__ __forceinline__ float sigm(float v) { return 1.0f / (1.0f + expf(-v)); }

__device__ __forceinline__ uint32_t smem_u32(const void* p) {
    uint32_t a;
    asm("{ .reg .u64 t; cvta.to.shared.u64 t, %1; cvt.u32.u64 %0, t; }" : "=r"(a) : "l"(p));
    return a;
}

#define LDSM_X4(r0, r1, r2, r3, addr) \
    asm volatile("ldmatrix.sync.aligned.m8n8.x4.shared.b16 {%0,%1,%2,%3}, [%4];" \
                 : "=r"(r0), "=r"(r1), "=r"(r2), "=r"(r3) : "r"(addr))
#define LDSM_X2(r0, r1, addr) \
    asm volatile("ldmatrix.sync.aligned.m8n8.x2.shared.b16 {%0,%1}, [%2];" \
                 : "=r"(r0), "=r"(r1) : "r"(addr))
#define MMA_BF16(d, a0, a1, a2, a3, b0, b1) \
    asm volatile("mma.sync.aligned.m16n8k16.row.col.f32.bf16.bf16.f32 " \
                 "{%0,%1,%2,%3}, {%4,%5,%6,%7}, {%8,%9}, {%0,%1,%2,%3};" \
                 : "+f"((d)[0]), "+f"((d)[1]), "+f"((d)[2]), "+f"((d)[3]) \
                 : "r"(a0), "r"(a1), "r"(a2), "r"(a3), "r"(b0), "r"(b1))

// ---------------------------------------------------------------------------
// Weight prep: transpose + bf16 hi/lo split of the 4 weight matrices.
// ---------------------------------------------------------------------------
__global__ void prep_kernel(const float* __restrict__ W_iou,
                            const float* __restrict__ U_iou,
                            const float* __restrict__ W_f,
                            const float* __restrict__ U_f) {
    int gid = blockIdx.x * blockDim.x + threadIdx.x;   // < 524288
    float v; __nv_bfloat16 *phi, *plo; int oi;
    if (gid < 196608) {                    // W_iou^T
        int n = gid >> 8, k = gid & 255;
        v = W_iou[k * 768 + n]; phi = g_wiou_hi; plo = g_wiou_lo; oi = gid;
    } else if (gid < 393216) {             // U_iou^T
        int t = gid - 196608; int n = t >> 8, k = t & 255;
        v = U_iou[k * 768 + n]; phi = g_uiou_hi; plo = g_uiou_lo; oi = t;
    } else if (gid < 458752) {             // W_f^T
        int t = gid - 393216; int n = t >> 8, k = t & 255;
        v = W_f[k * 256 + n]; phi = g_wf_hi; plo = g_wf_lo; oi = t;
    } else if (gid < 524288) {             // U_f^T
        int t = gid - 458752; int n = t >> 8, k = t & 255;
        v = U_f[k * 256 + n]; phi = g_uf_hi; plo = g_uf_lo; oi = t;
    } else return;
    __nv_bfloat16 hi = __float2bfloat16_rn(v);
    phi[oi] = hi;
    plo[oi] = __float2bfloat16_rn(v - __bfloat162float(hi));
}

// ---------------------------------------------------------------------------
// HMMA bf16x3 GEMM.  C[M,Ncols] = A'(fp32, split on the fly) @ Wt^T (+bias)
// K = 256, two 128-wide chunks. Tile 128x128, 256 threads = 8 warps (2m x 4n),
// warp tile 64x32, mma.sync m16n8k16. Smem rows padded to 136 bf16 elements.
//   A row m = b*nlev + k :  row = b*astride + (pairsum ? 2k (+sibling sum) : k)
// ---------------------------------------------------------------------------
#define LDSB  136                 // padded row length (bf16 elems)
#define TILE_B (128 * LDSB * 2)   // bytes per tile (34816)
#define OFF_AHI 0
#define OFF_ALO (TILE_B)
#define OFF_BHI (2 * TILE_B)
#define OFF_BLO (3 * TILE_B)
#define SMEM_TOTAL (4 * TILE_B)   // 139264

__global__ __launch_bounds__(256, 1)
void gemm_hmma(const float* __restrict__ A,
               const __nv_bfloat16* __restrict__ Bhi,
               const __nv_bfloat16* __restrict__ Blo,
               const float* __restrict__ bias, float* __restrict__ C,
               int M, int Ncols, int nlev, int astride, int pairsum) {
    extern __shared__ char smem[];
    const uint32_t sb = smem_u32(smem);
    const int tid = threadIdx.x;
    const int wid = tid >> 5;
    const int lid = tid & 31;
    const int wm = wid >> 2;       // 0..1
    const int wn = wid & 3;        // 0..3
    const int m0 = blockIdx.y * 128;
    const int n0 = blockIdx.x * 128;

    float acc[4][4][4];
#pragma unroll
    for (int mi = 0; mi < 4; mi++)
#pragma unroll
        for (int ni = 0; ni < 4; ni++)
#pragma unroll
            for (int q = 0; q < 4; q++) acc[mi][ni][q] = 0.0f;

    // loader map: 8 threads per row (16 k each), 32 rows per pass, 4 passes
    const int rbase = tid >> 3;          // 0..31
    const int kseg = (tid & 7) * 16;     // 0..112

    // ldmatrix lane address components
    const int arow = lid & 15, ahalf = lid >> 4;          // A: x4
    const int brow = lid & 7,  bhalf = (lid >> 3) & 1;    // B: x2 (lanes 0-15)

    for (int chunk = 0; chunk < 2; chunk++) {
        if (chunk) __syncthreads();   // all warps done with previous tiles

        // ---- load + split A, load B ----
#pragma unroll
        for (int p = 0; p < 4; p++) {
            const int r = p * 32 + rbase;
            const uint32_t so = (uint32_t)(r * LDSB + kseg) * 2;

            // A: fp32 -> bf16 hi/lo
            float va[16];
            const int gm = m0 + r;
            if (gm < M) {
                int b = gm / nlev;
                int k = gm - b * nlev;
                size_t row = (size_t)b * astride + (pairsum ? 2 * k : k);
                const float* ap = A + row * 256 + chunk * 128 + kseg;
#pragma unroll
                for (int q = 0; q < 4; q++) *(float4*)&va[q * 4] = *(const float4*)(ap + q * 4);
                if (pairsum) {
#pragma unroll
                    for (int q = 0; q < 4; q++) {
                        float4 v2 = *(const float4*)(ap + 256 + q * 4);
                        va[q*4+0] += v2.x; va[q*4+1] += v2.y; va[q*4+2] += v2.z; va[q*4+3] += v2.w;
                    }
                }
            } else {
#pragma unroll
                for (int q = 0; q < 16; q++) va[q] = 0.0f;
            }
            uint32_t hi[8], lo[8];
#pragma unroll
            for (int q = 0; q < 8; q++) {
                float a0 = va[2*q], a1 = va[2*q+1];
                __nv_bfloat162 h2 = __floats2bfloat162_rn(a0, a1);
                hi[q] = *(uint32_t*)&h2;
                float r0 = a0 - __bfloat162float(__low2bfloat16(h2));
                float r1 = a1 - __bfloat162float(__high2bfloat16(h2));
                __nv_bfloat162 l2 = __floats2bfloat162_rn(r0, r1);
                lo[q] = *(uint32_t*)&l2;
            }
            *(uint4*)(smem + OFF_AHI + so)      = make_uint4(hi[0], hi[1], hi[2], hi[3]);
            *(uint4*)(smem + OFF_AHI + so + 16) = make_uint4(hi[4], hi[5], hi[6], hi[7]);
            *(uint4*)(smem + OFF_ALO + so)      = make_uint4(lo[0], lo[1], lo[2], lo[3]);
            *(uint4*)(smem + OFF_ALO + so + 16) = make_uint4(lo[4], lo[5], lo[6], lo[7]);

            // B: pre-split bf16, rows = output columns (n-major, k contiguous)
            {
                const int n = n0 + r;
                const __nv_bfloat16* bp = Bhi + (size_t)n * 256 + chunk * 128 + kseg;
                *(uint4*)(smem + OFF_BHI + so)      = *(const uint4*)(bp);
                *(uint4*)(smem + OFF_BHI + so + 16) = *(const uint4*)(bp + 8);
                const __nv_bfloat16* bq = Blo + (size_t)n * 256 + chunk * 128 + kseg;
                *(uint4*)(smem + OFF_BLO + so)      = *(const uint4*)(bq);
                *(uint4*)(smem + OFF_BLO + so + 16) = *(const uint4*)(bq + 8);
            }
        }
        __syncthreads();

        // ---- compute: 8 k-steps of m16n8k16, 3 split terms ----
#pragma unroll
        for (int ks = 0; ks < 8; ks++) {
            // B fragments for this k-step (4 n-subtiles, hi & lo)
            uint32_t bh[4][2], bl[4][2];
#pragma unroll
            for (int ni = 0; ni < 4; ni++) {
                uint32_t ba = sb + (uint32_t)((wn * 32 + ni * 8 + brow) * LDSB
                                              + ks * 16 + bhalf * 8) * 2;
                LDSM_X2(bh[ni][0], bh[ni][1], ba + OFF_BHI);
                LDSM_X2(bl[ni][0], bl[ni][1], ba + OFF_BLO);
            }
#pragma unroll
            for (int mi = 0; mi < 4; mi++) {
                uint32_t aa = sb + (uint32_t)((wm * 64 + mi * 16 + arow) * LDSB
                                              + ks * 16 + ahalf * 8) * 2;
                uint32_t ah0, ah1, ah2, ah3, al0, al1, al2, al3;
                LDSM_X4(ah0, ah1, ah2, ah3, aa + OFF_AHI);
                LDSM_X4(al0, al1, al2, al3, aa + OFF_ALO);
#pragma unroll
                for (int ni = 0; ni < 4; ni++) {
                    MMA_BF16(acc[mi][ni], ah0, ah1, ah2, ah3, bh[ni][0], bh[ni][1]);
                    MMA_BF16(acc[mi][ni], ah0, ah1, ah2, ah3, bl[ni][0], bl[ni][1]);
                    MMA_BF16(acc[mi][ni], al0, al1, al2, al3, bh[ni][0], bh[ni][1]);
                }
            }
        }
    }

    // ---- epilogue ----
    const int crow = lid >> 2;          // 0..7
    const int ccol = (lid & 3) * 2;     // 0,2,4,6
#pragma unroll
    for (int mi = 0; mi < 4; mi++) {
        const int gr0 = m0 + wm * 64 + mi * 16 + crow;
#pragma unroll
        for (int ni = 0; ni < 4; ni++) {
            const int gc = n0 + wn * 32 + ni * 8 + ccol;
            float b0 = 0.f, b1 = 0.f;
            if (bias) { b0 = bias[gc]; b1 = bias[gc + 1]; }
            if (gr0 < M) {
                float2 v = make_float2(acc[mi][ni][0] + b0, acc[mi][ni][1] + b1);
                *(float2*)(C + (size_t)gr0 * Ncols + gc) = v;
            }
            if (gr0 + 8 < M) {
                float2 v = make_float2(acc[mi][ni][2] + b0, acc[mi][ni][3] + b1);
                *(float2*)(C + (size_t)(gr0 + 8) * Ncols + gc) = v;
            }
        }
    }
}

// ---------------------------------------------------------------------------
// Leaf activation: c = sig(i)*tanh(u); h = sig(o)*tanh(c)  -> ping buffer 0
// ---------------------------------------------------------------------------
__global__ void leaf_kernel() {
    size_t gid = (size_t)blockIdx.x * blockDim.x + threadIdx.x;
    int j = (int)(gid & 255);
    size_t m = gid >> 8;
    int b = (int)(m >> 14);
    int k = (int)(m & 16383);
    size_t prerow = ((size_t)b * NNODE + (LLEAF - 1) + k) * 768;
    float iv = g_pre_iou[prerow + j];
    float ov = g_pre_iou[prerow + 256 + j];
    float uv = g_pre_iou[prerow + 512 + j];
    float c = sigm(iv) * tanhf(uv);
    float h = sigm(ov) * tanhf(c);
    size_t idx = ((size_t)b * MAXN + k) * DH + j;
    g_h[0][idx] = h;
    g_c[0][idx] = c;
}

// ---------------------------------------------------------------------------
// Per-level combine: gates + forget-weighted child cells.
// ---------------------------------------------------------------------------
__global__ void combine_kernel(int n, int pin, int pout) {
    size_t gid = (size_t)blockIdx.x * blockDim.x + threadIdx.x;
    size_t total = (size_t)BDIM * n * DH;
    if (gid >= total) return;
    int j = (int)(gid & 255);
    size_t m = gid >> 8;
    int b = (int)(m / (unsigned)n);
    int k = (int)(m - (size_t)b * n);
    int node = (n - 1) + k;

    size_t prow = ((size_t)b * NNODE + node) * 768;
    size_t grow = m * 768;
    float iv = g_pre_iou[prow + j]       + g_giou[grow + j];
    float ov = g_pre_iou[prow + 256 + j] + g_giou[grow + 256 + j];
    float uv = g_pre_iou[prow + 512 + j] + g_giou[grow + 512 + j];
    float fb = g_pre_f[((size_t)b * NINT + node) * 256 + j];

    size_t gf0 = ((size_t)b * (2 * n) + 2 * k) * 256 + j;
    float f0 = sigm(fb + g_gf[gf0]);
    float f1 = sigm(fb + g_gf[gf0 + 256]);

    size_t cbase = ((size_t)b * MAXN + 2 * k) * 256 + j;
    float c0 = g_c[pin][cbase];
    float c1 = g_c[pin][cbase + 256];

    float cn = sigm(iv) * tanhf(uv) + f0 * c0 + f1 * c1;
    float hn = sigm(ov) * tanhf(cn);

    size_t outi = ((size_t)b * MAXN + k) * 256 + j;
    g_h[pout][outi] = hn;
    g_c[pout][outi] = cn;
}

// ---------------------------------------------------------------------------
__global__ void final_kernel(int p, float* __restrict__ out) {
    int gid = blockIdx.x * blockDim.x + threadIdx.x;
    if (gid >= BDIM * 512) return;
    int b = gid >> 9;
    int j = gid & 511;
    size_t base = ((size_t)b * MAXN) * 256;
    out[gid] = (j < 256) ? g_h[p][base + j] : g_c[p][base + j - 256];
}

// ---------------------------------------------------------------------------
extern "C" void kernel_launch(void* const* d_in, const int* in_sizes, int n_in,
                              void* d_out, int out_size) {
    const float* x     = (const float*)d_in[0];
    const float* W_iou = (const float*)d_in[1];
    const float* b_iou = (const float*)d_in[2];
    const float* U_iou = (const float*)d_in[3];
    const float* W_f   = (const float*)d_in[4];
    const float* b_f   = (const float*)d_in[5];
    const float* U_f   = (const float*)d_in[6];
    float* out = (float*)d_out;

    float *pPreIou, *pPreF, *pH, *pGiou, *pGf;
    cudaGetSymbolAddress((void**)&pPreIou, g_pre_iou);
    cudaGetSymbolAddress((void**)&pPreF, g_pre_f);
    cudaGetSymbolAddress((void**)&pH, g_h);
    cudaGetSymbolAddress((void**)&pGiou, g_giou);
    cudaGetSymbolAddress((void**)&pGf, g_gf);
    __nv_bfloat16 *pWiouH, *pWiouL, *pUiouH, *pUiouL, *pWfH, *pWfL, *pUfH, *pUfL;
    cudaGetSymbolAddress((void**)&pWiouH, g_wiou_hi);
    cudaGetSymbolAddress((void**)&pWiouL, g_wiou_lo);
    cudaGetSymbolAddress((void**)&pUiouH, g_uiou_hi);
    cudaGetSymbolAddress((void**)&pUiouL, g_uiou_lo);
    cudaGetSymbolAddress((void**)&pWfH, g_wf_hi);
    cudaGetSymbolAddress((void**)&pWfL, g_wf_lo);
    cudaGetSymbolAddress((void**)&pUfH, g_uf_hi);
    cudaGetSymbolAddress((void**)&pUfL, g_uf_lo);

    cudaFuncSetAttribute(gemm_hmma, cudaFuncAttributeMaxDynamicSharedMemorySize,
                         SMEM_TOTAL);

    // 0) transpose + split weights
    prep_kernel<<<2048, 256>>>(W_iou, U_iou, W_f, U_f);

    // 1) input projections
    {
        int M = BDIM * NNODE;  // 262136
        dim3 grid(768 / 128, (M + 127) / 128);
        gemm_hmma<<<grid, 256, SMEM_TOTAL>>>(x, pWiouH, pWiouL, b_iou, pPreIou,
                                             M, 768, NNODE, NNODE, 0);
    }
    {
        int M = BDIM * NINT;   // 131064
        dim3 grid(256 / 128, (M + 127) / 128);
        gemm_hmma<<<grid, 256, SMEM_TOTAL>>>(x, pWfH, pWfL, b_f, pPreF,
                                             M, 256, NINT, NNODE, 0);
    }

    // 2) leaf activations
    leaf_kernel<<<(BDIM * LLEAF * DH) / 256, 256>>>();

    // 3) 14 levels
    int p = 0;
    for (int n = LLEAF / 2; n >= 1; n >>= 1) {
        int pin = p, pout = 1 - p;
        const float* hin = pH + (size_t)pin * 33554432;

        int M1 = BDIM * n;
        dim3 g1(768 / 128, (M1 + 127) / 128);
        gemm_hmma<<<g1, 256, SMEM_TOTAL>>>(hin, pUiouH, pUiouL, nullptr, pGiou,
                                           M1, 768, n, MAXN, 1);

        int M2 = BDIM * 2 * n;
        dim3 g2(256 / 128, (M2 + 127) / 128);
        gemm_hmma<<<g2, 256, SMEM_TOTAL>>>(hin, pUfH, pUfL, nullptr, pGf,
                                           M2, 256, 2 * n, MAXN, 0);

        size_t tot = (size_t)BDIM * n * DH;
        combine_kernel<<<(unsigned)((tot + 255) / 256), 256>>>(n, pin, pout);
        p = pout;
    }

    // 4) emit root h,c
    final_kernel<<<16, 256>>>(p, out);
}

// round 11
// speedup vs baseline: 2.0442x; 1.1362x over previous
#include <cuda_runtime.h>
#include <cuda_bf16.h>
#include <math.h>
#include <stdint.h>

// Problem constants
#define BDIM   8
#define LLEAF  16384
#define NNODE  32767      // 2*L - 1
#define DH     256
#define MAXN   16384
#define XELEMS 67106816ULL   // 8*32767*256

// ---------------------------------------------------------------------------
// Static device scratch
// ---------------------------------------------------------------------------
__device__ float g_pre[268427264];          // 8*32767*1024 : x@[Wiou|Wf]+bias
__device__ float g_gproj[134217728];        // 8*16384*1024 : h_child@[Uiou|Uf]
__device__ float g_c[2][33554432];          // ping-pong c (fp32)
__device__ __nv_bfloat16 g_hhi[2][33554432], g_hlo[2][33554432];  // split h
__device__ __nv_bfloat16 g_xhi[67106816], g_xlo[67106816];        // split x

// Packed transposed weights: rows = output col (1024), cols = k (256)
__device__ __nv_bfloat16 g_wcat_hi[262144], g_wcat_lo[262144];
__device__ __nv_bfloat16 g_ucat_hi[262144], g_ucat_lo[262144];
__device__ float g_bias[1024];

__device__ __forceinline__ float sigm(float v) { return 1.0f / (1.0f + expf(-v)); }

__device__ __forceinline__ uint32_t smem_u32(const void* p) {
    uint32_t a;
    asm("{ .reg .u64 t; cvta.to.shared.u64 t, %1; cvt.u32.u64 %0, t; }" : "=r"(a) : "l"(p));
    return a;
}

#define LDSM_X4(r0, r1, r2, r3, addr) \
    asm volatile("ldmatrix.sync.aligned.m8n8.x4.shared.b16 {%0,%1,%2,%3}, [%4];" \
                 : "=r"(r0), "=r"(r1), "=r"(r2), "=r"(r3) : "r"(addr))
#define LDSM_X2(r0, r1, addr) \
    asm volatile("ldmatrix.sync.aligned.m8n8.x2.shared.b16 {%0,%1}, [%2];" \
                 : "=r"(r0), "=r"(r1) : "r"(addr))
#define MMA_BF16(d, a0, a1, a2, a3, b0, b1) \
    asm volatile("mma.sync.aligned.m16n8k16.row.col.f32.bf16.bf16.f32 " \
                 "{%0,%1,%2,%3}, {%4,%5,%6,%7}, {%8,%9}, {%0,%1,%2,%3};" \
                 : "+f"((d)[0]), "+f"((d)[1]), "+f"((d)[2]), "+f"((d)[3]) \
                 : "r"(a0), "r"(a1), "r"(a2), "r"(a3), "r"(b0), "r"(b1))
#define CP_ASYNC(dst, src, sz) \
    asm volatile("cp.async.cg.shared.global [%0], [%1], 16, %2;" \
                 :: "r"(dst), "l"(src), "r"(sz))
#define CP_COMMIT() asm volatile("cp.async.commit_group;")
#define CP_WAIT1()  asm volatile("cp.async.wait_group 1;")
#define CP_WAIT0()  asm volatile("cp.async.wait_group 0;")

// ---------------------------------------------------------------------------
// Weight prep: pack [W_iou|W_f] and [U_iou|U_f] transposed, bf16 hi/lo split.
// ---------------------------------------------------------------------------
__global__ void prep_kernel(const float* __restrict__ W_iou,
                            const float* __restrict__ b_iou,
                            const float* __restrict__ U_iou,
                            const float* __restrict__ W_f,
                            const float* __restrict__ b_f,
                            const float* __restrict__ U_f) {
    int gid = blockIdx.x * blockDim.x + threadIdx.x;   // < 524288
    if (gid < 1024) g_bias[gid] = (gid < 768) ? b_iou[gid] : b_f[gid - 768];
    float v; __nv_bfloat16 *phi, *plo; int oi;
    if (gid < 262144) {            // Wcat^T
        int n = gid >> 8, k = gid & 255;
        v = (n < 768) ? W_iou[k * 768 + n] : W_f[k * 256 + (n - 768)];
        phi = g_wcat_hi; plo = g_wcat_lo; oi = gid;
    } else {                       // Ucat^T
        int t = gid - 262144; int n = t >> 8, k = t & 255;
        v = (n < 768) ? U_iou[k * 768 + n] : U_f[k * 256 + (n - 768)];
        phi = g_ucat_hi; plo = g_ucat_lo; oi = t;
    }
    __nv_bfloat16 hi = __float2bfloat16_rn(v);
    phi[oi] = hi;
    plo[oi] = __float2bfloat16_rn(v - __bfloat162float(hi));
}

// ---------------------------------------------------------------------------
// Split x (fp32) into bf16 hi/lo arrays.
// ---------------------------------------------------------------------------
__global__ void split_x_kernel(const float* __restrict__ x) {
    size_t base = ((size_t)blockIdx.x * 256 + threadIdx.x) * 4;
    if (base >= XELEMS) return;
    float4 v = *(const float4*)(x + base);
    __nv_bfloat162 h0 = __floats2bfloat162_rn(v.x, v.y);
    __nv_bfloat162 h1 = __floats2bfloat162_rn(v.z, v.w);
    __nv_bfloat162 l0 = __floats2bfloat162_rn(
        v.x - __bfloat162float(__low2bfloat16(h0)),
        v.y - __bfloat162float(__high2bfloat16(h0)));
    __nv_bfloat162 l1 = __floats2bfloat162_rn(
        v.z - __bfloat162float(__low2bfloat16(h1)),
        v.w - __bfloat162float(__high2bfloat16(h1)));
    *(uint2*)(g_xhi + base) = make_uint2(*(uint32_t*)&h0, *(uint32_t*)&h1);
    *(uint2*)(g_xlo + base) = make_uint2(*(uint32_t*)&l0, *(uint32_t*)&l1);
}

// ---------------------------------------------------------------------------
// HMMA bf16x3 GEMM, cp.async double-buffered.
//   C[M,1024] = A' @ Wt^T (+bias); K=256 in four 64-chunks, 2 stages.
//   Tile 128x128, 256 threads (2x4 warps), warp tile 64x32.
//   A row m: lgn<0 -> row=m; else row=(m>>lgn)*astride + (m & ((1<<lgn)-1)).
// Smem rows padded to 72 bf16 (144 B) -> conflict-free ldmatrix.
// ---------------------------------------------------------------------------
#define LDSC    72
#define ARR_B   (128 * 144)          // 18432 bytes per array per stage
#define OFF_AHI 0
#define OFF_ALO ARR_B
#define OFF_BHI (2 * ARR_B)
#define OFF_BLO (3 * ARR_B)
#define STAGE_B (4 * ARR_B)          // 73728
#define SMEM_TOTAL (2 * STAGE_B)     // 147456

struct LoadCtx {
    const __nv_bfloat16 *sAhi[4], *sAlo[4], *sBhi[4], *sBlo[4];
    uint32_t szA[4], doff[4];
};

__device__ __forceinline__ void issue_stage(const LoadCtx& L, uint32_t sbase, int chunk) {
#pragma unroll
    for (int p = 0; p < 4; p++) {
        CP_ASYNC(sbase + OFF_AHI + L.doff[p], L.sAhi[p] + chunk * 64, L.szA[p]);
        CP_ASYNC(sbase + OFF_ALO + L.doff[p], L.sAlo[p] + chunk * 64, L.szA[p]);
        CP_ASYNC(sbase + OFF_BHI + L.doff[p], L.sBhi[p] + chunk * 64, 16u);
        CP_ASYNC(sbase + OFF_BLO + L.doff[p], L.sBlo[p] + chunk * 64, 16u);
    }
    CP_COMMIT();
}

__global__ __launch_bounds__(256, 1)
void gemm_hmma(const __nv_bfloat16* __restrict__ Ahi,
               const __nv_bfloat16* __restrict__ Alo,
               const __nv_bfloat16* __restrict__ Bhi,
               const __nv_bfloat16* __restrict__ Blo,
               const float* __restrict__ bias, float* __restrict__ C,
               int M, int lgn, int astride) {
    extern __shared__ char smem[];
    const uint32_t sb = smem_u32(smem);
    const int tid = threadIdx.x;
    const int wid = tid >> 5, lid = tid & 31;
    const int wm = wid >> 2, wn = wid & 3;
    const int m0 = blockIdx.y * 128;
    const int n0 = blockIdx.x * 128;

    float acc[4][4][4];
#pragma unroll
    for (int mi = 0; mi < 4; mi++)
#pragma unroll
        for (int ni = 0; ni < 4; ni++)
#pragma unroll
            for (int q = 0; q < 4; q++) acc[mi][ni][q] = 0.0f;

    // ---- loader context: 4 rows/thread, 16B segment each ----
    LoadCtx L;
    {
        const int rs = tid >> 3;
        const int seg = tid & 7;
#pragma unroll
        for (int p = 0; p < 4; p++) {
            int r = rs + 32 * p;
            L.doff[p] = (uint32_t)(r * 144 + seg * 16);
            int gm = m0 + r;
            size_t row = 0;
            if (gm < M) {
                if (lgn < 0) row = (size_t)gm;
                else {
                    int b = gm >> lgn;
                    int k = gm & ((1 << lgn) - 1);
                    row = (size_t)b * astride + k;
                }
                L.szA[p] = 16;
            } else L.szA[p] = 0;
            L.sAhi[p] = Ahi + row * 256 + seg * 8;
            L.sAlo[p] = Alo + row * 256 + seg * 8;
            int n = n0 + r;
            L.sBhi[p] = Bhi + (size_t)n * 256 + seg * 8;
            L.sBlo[p] = Blo + (size_t)n * 256 + seg * 8;
        }
    }

    const int arow = lid & 15, ahalf = lid >> 4;
    const int brow = lid & 7,  bhalf = (lid >> 3) & 1;

    issue_stage(L, sb, 0);
    issue_stage(L, sb + STAGE_B, 1);

#pragma unroll
    for (int c = 0; c < 4; c++) {
        if (c < 3) CP_WAIT1(); else CP_WAIT0();
        __syncthreads();
        const uint32_t sbase = sb + (uint32_t)(c & 1) * STAGE_B;

#pragma unroll
        for (int ks = 0; ks < 4; ks++) {
            uint32_t bh[4][2], bl[4][2];
#pragma unroll
            for (int ni = 0; ni < 4; ni++) {
                uint32_t ba = sbase + (uint32_t)((wn * 32 + ni * 8 + brow) * 144
                                                 + ks * 32 + bhalf * 16);
                LDSM_X2(bh[ni][0], bh[ni][1], ba + OFF_BHI);
                LDSM_X2(bl[ni][0], bl[ni][1], ba + OFF_BLO);
            }
#pragma unroll
            for (int mi = 0; mi < 4; mi++) {
                uint32_t aa = sbase + (uint32_t)((wm * 64 + mi * 16 + arow) * 144
                                                 + ks * 32 + ahalf * 16);
                uint32_t ah0, ah1, ah2, ah3, al0, al1, al2, al3;
                LDSM_X4(ah0, ah1, ah2, ah3, aa + OFF_AHI);
                LDSM_X4(al0, al1, al2, al3, aa + OFF_ALO);
#pragma unroll
                for (int ni = 0; ni < 4; ni++) {
                    MMA_BF16(acc[mi][ni], ah0, ah1, ah2, ah3, bh[ni][0], bh[ni][1]);
                    MMA_BF16(acc[mi][ni], ah0, ah1, ah2, ah3, bl[ni][0], bl[ni][1]);
                    MMA_BF16(acc[mi][ni], al0, al1, al2, al3, bh[ni][0], bh[ni][1]);
                }
            }
        }
        __syncthreads();
        if (c < 2) issue_stage(L, sbase, c + 2);
    }

    // ---- epilogue ----
    const int crow = lid >> 2;
    const int ccol = (lid & 3) * 2;
#pragma unroll
    for (int mi = 0; mi < 4; mi++) {
        const int gr0 = m0 + wm * 64 + mi * 16 + crow;
#pragma unroll
        for (int ni = 0; ni < 4; ni++) {
            const int gc = n0 + wn * 32 + ni * 8 + ccol;
            float b0 = 0.f, b1 = 0.f;
            if (bias) { b0 = bias[gc]; b1 = bias[gc + 1]; }
            if (gr0 < M) {
                float2 v = make_float2(acc[mi][ni][0] + b0, acc[mi][ni][1] + b1);
                *(float2*)(C + (size_t)gr0 * 1024 + gc) = v;
            }
            if (gr0 + 8 < M) {
                float2 v = make_float2(acc[mi][ni][2] + b0, acc[mi][ni][3] + b1);
                *(float2*)(C + (size_t)(gr0 + 8) * 1024 + gc) = v;
            }
        }
    }
}

// ---------------------------------------------------------------------------
// Leaf activation -> ping buffer 0 (h split bf16 hi/lo, c fp32)
// ---------------------------------------------------------------------------
__global__ void leaf_kernel() {
    size_t gid = (size_t)blockIdx.x * blockDim.x + threadIdx.x;
    int j = (int)(gid & 255);
    size_t m = gid >> 8;
    int b = (int)(m >> 14);
    int k = (int)(m & 16383);
    size_t prerow = ((size_t)b * NNODE + (LLEAF - 1) + k) * 1024;
    float iv = g_pre[prerow + j];
    float ov = g_pre[prerow + 256 + j];
    float uv = g_pre[prerow + 512 + j];
    float c = sigm(iv) * tanhf(uv);
    float h = sigm(ov) * tanhf(c);
    size_t idx = ((size_t)b * MAXN + k) * DH + j;
    g_c[0][idx] = c;
    __nv_bfloat16 hh = __float2bfloat16_rn(h);
    g_hhi[0][idx] = hh;
    g_hlo[0][idx] = __float2bfloat16_rn(h - __bfloat162float(hh));
}

// ---------------------------------------------------------------------------
// Per-level combine. gproj rows = per-child [iou(768) | f(256)] projections.
// ---------------------------------------------------------------------------
__global__ void combine_kernel(int n, int pin, int pout) {
    size_t gid = (size_t)blockIdx.x * blockDim.x + threadIdx.x;
    size_t total = (size_t)BDIM * n * DH;
    if (gid >= total) return;
    int j = (int)(gid & 255);
    size_t m = gid >> 8;
    int b = (int)(m / (unsigned)n);
    int k = (int)(m - (size_t)b * n);
    int node = (n - 1) + k;

    size_t prow = ((size_t)b * NNODE + node) * 1024;
    size_t g0 = ((size_t)b * (2 * n) + 2 * k) * 1024;

    float iv = g_pre[prow + j]       + g_gproj[g0 + j]       + g_gproj[g0 + 1024 + j];
    float ov = g_pre[prow + 256 + j] + g_gproj[g0 + 256 + j] + g_gproj[g0 + 1280 + j];
    float uv = g_pre[prow + 512 + j] + g_gproj[g0 + 512 + j] + g_gproj[g0 + 1536 + j];
    float fb = g_pre[prow + 768 + j];
    float f0 = sigm(fb + g_gproj[g0 + 768 + j]);
    float f1 = sigm(fb + g_gproj[g0 + 1792 + j]);

    size_t cbase = ((size_t)b * MAXN + 2 * k) * 256 + j;
    float c0 = g_c[pin][cbase];
    float c1 = g_c[pin][cbase + 256];

    float cn = sigm(iv) * tanhf(uv) + f0 * c0 + f1 * c1;
    float hn = sigm(ov) * tanhf(cn);

    size_t o = ((size_t)b * MAXN + k) * 256 + j;
    g_c[pout][o] = cn;
    __nv_bfloat16 hh = __float2bfloat16_rn(hn);
    g_hhi[pout][o] = hh;
    g_hlo[pout][o] = __float2bfloat16_rn(hn - __bfloat162float(hh));
}

// ---------------------------------------------------------------------------
__global__ void final_kernel(int p, float* __restrict__ out) {
    int gid = blockIdx.x * blockDim.x + threadIdx.x;
    if (gid >= BDIM * 512) return;
    int b = gid >> 9;
    int j = gid & 511;
    size_t base = ((size_t)b * MAXN) * 256;
    if (j < 256) {
        out[gid] = __bfloat162float(g_hhi[p][base + j])
                 + __bfloat162float(g_hlo[p][base + j]);
    } else {
        out[gid] = g_c[p][base + j - 256];
    }
}

// ---------------------------------------------------------------------------
extern "C" void kernel_launch(void* const* d_in, const int* in_sizes, int n_in,
                              void* d_out, int out_size) {
    const float* x     = (const float*)d_in[0];
    const float* W_iou = (const float*)d_in[1];
    const float* b_iou = (const float*)d_in[2];
    const float* U_iou = (const float*)d_in[3];
    const float* W_f   = (const float*)d_in[4];
    const float* b_f   = (const float*)d_in[5];
    const float* U_f   = (const float*)d_in[6];
    float* out = (float*)d_out;

    float *pPre, *pGproj, *pBias;
    cudaGetSymbolAddress((void**)&pPre, g_pre);
    cudaGetSymbolAddress((void**)&pGproj, g_gproj);
    cudaGetSymbolAddress((void**)&pBias, g_bias);
    __nv_bfloat16 *pXhi, *pXlo, *pHhi, *pHlo, *pWH, *pWL, *pUH, *pUL;
    cudaGetSymbolAddress((void**)&pXhi, g_xhi);
    cudaGetSymbolAddress((void**)&pXlo, g_xlo);
    cudaGetSymbolAddress((void**)&pHhi, g_hhi);
    cudaGetSymbolAddress((void**)&pHlo, g_hlo);
    cudaGetSymbolAddress((void**)&pWH, g_wcat_hi);
    cudaGetSymbolAddress((void**)&pWL, g_wcat_lo);
    cudaGetSymbolAddress((void**)&pUH, g_ucat_hi);
    cudaGetSymbolAddress((void**)&pUL, g_ucat_lo);

    cudaFuncSetAttribute(gemm_hmma, cudaFuncAttributeMaxDynamicSharedMemorySize,
                         SMEM_TOTAL);

    // 0) weight pack + x split
    prep_kernel<<<2048, 256>>>(W_iou, b_iou, U_iou, W_f, b_f, U_f);
    split_x_kernel<<<65534, 256>>>(x);

    // 1) pre = x @ [Wiou|Wf] + bias, all nodes  [B*NNODE, 1024]
    {
        int M = BDIM * NNODE;  // 262136
        dim3 grid(8, (M + 127) / 128);
        gemm_hmma<<<grid, 256, SMEM_TOTAL>>>(pXhi, pXlo, pWH, pWL, pBias, pPre,
                                             M, -1, 0);
    }

    // 2) leaf activations -> ping buffer 0
    leaf_kernel<<<(BDIM * LLEAF * DH) / 256, 256>>>();

    // 3) 14 levels: one GEMM (all children x Ucat) + combine per level
    int p = 0;
    int lgn = 14;                         // log2(2n) for n = 8192
    for (int n = LLEAF / 2; n >= 1; n >>= 1, lgn--) {
        int pin = p, pout = 1 - p;
        const __nv_bfloat16* hhi = pHhi + (size_t)pin * 33554432;
        const __nv_bfloat16* hlo = pHlo + (size_t)pin * 33554432;

        int M = BDIM * 2 * n;             // all child rows
        dim3 g(8, (M + 127) / 128);
        gemm_hmma<<<g, 256, SMEM_TOTAL>>>(hhi, hlo, pUH, pUL, nullptr, pGproj,
                                          M, lgn, MAXN);

        size_t tot = (size_t)BDIM * n * DH;
        combine_kernel<<<(unsigned)((tot + 255) / 256), 256>>>(n, pin, pout);
        p = pout;
    }

    // 4) emit root h,c
    final_kernel<<<16, 256>>>(p, out);
}